// round 7
// baseline (speedup 1.0000x reference)
#include <cuda_runtime.h>
#include <cuda_fp16.h>
#include <cuda_bf16.h>
#include <cstdint>

#define NN   100000
#define EE   3200000
#define FIN  512
#define HH   64
#define CC   8

// ---------------- scratch (device globals; no runtime allocation) ----------
__device__ __half g_h1h[NN * HH];     // fp16(x @ W1)
__device__ float g_t2[NN * CC];       // dinv[d] * (relu(agg1 + b1) @ W2)
__device__ int   g_deg[NN];
__device__ float g_dinv[NN];
__device__ int   g_rowptr[NN + 1];
__device__ int   g_cursor[NN];
__device__ int   g_col[EE];
__device__ int   g_bsum[512];
__device__ int   g_boff[512];

// W1 pre-transposed to MMA-B layout: [chunk(8)][n(64)][PADK(72)] bf16, hi & lo
#define PADK 72
__device__ __nv_bfloat16 g_w1t_hi[8 * HH * PADK];
__device__ __nv_bfloat16 g_w1t_lo[8 * HH * PADK];

// ---------------- stream fork/join infra (host, created at load) ------------
static cudaStream_t g_s2 = nullptr;
static cudaEvent_t  g_evA = nullptr, g_evB = nullptr;
namespace {
struct StreamInit {
    StreamInit() {
        if (cudaStreamCreateWithFlags(&g_s2, cudaStreamNonBlocking) != cudaSuccess)
            g_s2 = nullptr;
        if (g_s2) {
            if (cudaEventCreateWithFlags(&g_evA, cudaEventDisableTiming) != cudaSuccess ||
                cudaEventCreateWithFlags(&g_evB, cudaEventDisableTiming) != cudaSuccess) {
                g_s2 = nullptr;
            }
        }
    }
};
StreamInit g_stream_init;
}

// ---------------- CSR construction ------------------------------------------
__global__ void k_hist(const int* __restrict__ dst, int e) {
    int i = blockIdx.x * blockDim.x + threadIdx.x;
    if (i < e) atomicAdd(&g_deg[dst[i]], 1);
}

__global__ void k_bsum(int n) {
    __shared__ int s[256];
    int t = threadIdx.x;
    int i = blockIdx.x * 256 + t;
    s[t] = (i < n) ? g_deg[i] : 0;
    __syncthreads();
    for (int o = 128; o > 0; o >>= 1) {
        if (t < o) s[t] += s[t + o];
        __syncthreads();
    }
    if (t == 0) g_bsum[blockIdx.x] = s[0];
}

__global__ void k_scan_bsum(int nb) {
    __shared__ int s[512];
    int t = threadIdx.x;
    int v = (t < nb) ? g_bsum[t] : 0;
    s[t] = v;
    __syncthreads();
    for (int o = 1; o < 512; o <<= 1) {
        int a = (t >= o) ? s[t - o] : 0;
        __syncthreads();
        s[t] += a;
        __syncthreads();
    }
    if (t < nb) g_boff[t] = s[t] - v;
}

__global__ void k_scan_final(int n, int e) {
    __shared__ int s[256];
    int t = threadIdx.x;
    int i = blockIdx.x * 256 + t;
    int v = (i < n) ? g_deg[i] : 0;
    s[t] = v;
    __syncthreads();
    for (int o = 1; o < 256; o <<= 1) {
        int a = (t >= o) ? s[t - o] : 0;
        __syncthreads();
        s[t] += a;
        __syncthreads();
    }
    if (i < n) {
        int excl = g_boff[blockIdx.x] + s[t] - v;
        g_rowptr[i] = excl;
        g_cursor[i] = excl;
        g_dinv[i]   = rsqrtf((float)(v + 1));
    }
    if (i == 0) g_rowptr[n] = e;
}

__global__ void k_scatter(const int* __restrict__ src,
                          const int* __restrict__ dst, int e) {
    int i = blockIdx.x * blockDim.x + threadIdx.x;
    if (i < e) {
        int d   = dst[i];
        int pos = atomicAdd(&g_cursor[d], 1);
        g_col[pos] = src[i];
    }
}

// ---------------- W1 -> bf16 hi/lo transposed image -------------------------
__global__ void k_prep_w1(const float* __restrict__ W1) {
    int idx = blockIdx.x * 256 + threadIdx.x;      // n*512 + kg
    if (idx >= HH * FIN) return;
    int nn = idx >> 9;
    int kg = idx & 511;
    float v = W1[(size_t)kg * HH + nn];
    __nv_bfloat16 hi = __float2bfloat16(v);
    __nv_bfloat16 lo = __float2bfloat16(v - __bfloat162float(hi));
    int chunk = kg >> 6, k = kg & 63;
    int o = (chunk * HH + nn) * PADK + k;
    g_w1t_hi[o] = hi;
    g_w1t_lo[o] = lo;
}

// ---------------- GEMM1: h1 = fp16(x @ W1) via HMMA bf16 split --------------
__device__ __forceinline__ void mma16816(float* c, uint32_t a0, uint32_t a1,
                                         uint32_t a2, uint32_t a3,
                                         uint32_t b0, uint32_t b1) {
    asm volatile(
        "mma.sync.aligned.m16n8k16.row.col.f32.bf16.bf16.f32 "
        "{%0,%1,%2,%3}, {%4,%5,%6,%7}, {%8,%9}, {%0,%1,%2,%3};"
        : "+f"(c[0]), "+f"(c[1]), "+f"(c[2]), "+f"(c[3])
        : "r"(a0), "r"(a1), "r"(a2), "r"(a3), "r"(b0), "r"(b1));
}

__device__ __forceinline__ uint32_t bf16x2_rn(float up, float lo) {
    uint32_t r;
    asm("cvt.rn.bf16x2.f32 %0, %1, %2;" : "=r"(r) : "f"(up), "f"(lo));
    return r;
}

__device__ __forceinline__ uint32_t smem_u32(const void* p) {
    uint32_t a;
    asm("{ .reg .u64 t; cvta.to.shared.u64 t, %1; cvt.u32.u64 %0, t; }"
        : "=r"(a) : "l"(p));
    return a;
}

#define LDSM4(r0, r1, r2, r3, addr)                                            \
    asm volatile("ldmatrix.sync.aligned.m8n8.x4.shared.b16 {%0,%1,%2,%3}, [%4];" \
                 : "=r"(r0), "=r"(r1), "=r"(r2), "=r"(r3) : "r"(addr))

#define SM_AHI 0
#define SM_ALO (128 * PADK)
#define SM_BHI (256 * PADK)
#define SM_BLO (320 * PADK)
#define SMEM_GEMM ((384 * PADK) * 2)

__global__ __launch_bounds__(256) void k_gemm1_mma(const float* __restrict__ x,
                                                   int n) {
    extern __shared__ __nv_bfloat16 sm[];
    int tid = threadIdx.x, wid = tid >> 5, lane = tid & 31;
    int t = lane & 3;
    int g = lane >> 2;
    int mBase = blockIdx.x * 128;

    uint32_t sb = smem_u32(sm);
    // ldmatrix per-lane row addresses: lanes 0-15 -> rows 0-15 (k lo half),
    // lanes 16-31 -> rows 0-15 (k hi half, +8 columns)
    int lrow = lane & 15, lsel = lane >> 4;
    uint32_t aoff = (uint32_t)(((wid * 16 + lrow) * PADK + lsel * 8) * 2);
    uint32_t boff0 = (uint32_t)(((0 * 16 + lrow) * PADK + lsel * 8) * 2);
    uint32_t boff1 = (uint32_t)(((1 * 16 + lrow) * PADK + lsel * 8) * 2);
    uint32_t boff2 = (uint32_t)(((2 * 16 + lrow) * PADK + lsel * 8) * 2);
    uint32_t boff3 = (uint32_t)(((3 * 16 + lrow) * PADK + lsel * 8) * 2);

    float acc[8][4];
#pragma unroll
    for (int i = 0; i < 8; i++)
#pragma unroll
        for (int j = 0; j < 4; j++) acc[i][j] = 0.f;

    for (int chunk = 0; chunk < FIN / 64; chunk++) {
        int kb = chunk * 64;
        if (chunk) __syncthreads();

        // ---- A tile: 128 rows x 64 k from x (fp32), split hi/lo (bf16x2 cvt)
#pragma unroll
        for (int l = 0; l < 8; l++) {
            int id  = tid + l * 256;
            int row = id >> 4;
            int col = (id & 15) * 4;
            float4 v = make_float4(0.f, 0.f, 0.f, 0.f);
            int gr = mBase + row;
            if (gr < n) v = *(const float4*)&x[(size_t)gr * FIN + kb + col];
            uint32_t uh0 = bf16x2_rn(v.y, v.x);
            uint32_t uh1 = bf16x2_rn(v.w, v.z);
            float h0f = __uint_as_float(uh0 << 16);
            float h1f = __uint_as_float(uh0 & 0xFFFF0000u);
            float h2f = __uint_as_float(uh1 << 16);
            float h3f = __uint_as_float(uh1 & 0xFFFF0000u);
            uint32_t ul0 = bf16x2_rn(v.y - h1f, v.x - h0f);
            uint32_t ul1 = bf16x2_rn(v.w - h3f, v.z - h2f);
            int o = row * PADK + col;
            *(uint2*)&sm[SM_AHI + o] = make_uint2(uh0, uh1);
            *(uint2*)&sm[SM_ALO + o] = make_uint2(ul0, ul1);
        }

        // ---- B tile: contiguous copy of pre-transposed image
        {
            const uint4* shi = (const uint4*)&g_w1t_hi[chunk * HH * PADK];
            const uint4* slo = (const uint4*)&g_w1t_lo[chunk * HH * PADK];
            uint4* dhi = (uint4*)&sm[SM_BHI];
            uint4* dlo = (uint4*)&sm[SM_BLO];
            for (int i = tid; i < HH * PADK / 8; i += 256) {
                dhi[i] = shi[i];
                dlo[i] = slo[i];
            }
        }
        __syncthreads();

#pragma unroll
        for (int ks = 0; ks < 4; ks++) {
            uint32_t kbyte = (uint32_t)(ks * 32);
            uint32_t ah0, ah1, ah2, ah3, al0, al1, al2, al3;
            LDSM4(ah0, ah1, ah2, ah3, sb + 2 * SM_AHI + aoff + kbyte);
            LDSM4(al0, al1, al2, al3, sb + 2 * SM_ALO + aoff + kbyte);
            uint32_t bofs[4] = {boff0, boff1, boff2, boff3};
#pragma unroll
            for (int p = 0; p < 4; p++) {
                uint32_t bhe0, bho0, bhe1, bho1;   // even nt (b0,b1), odd nt
                uint32_t ble0, blo0, ble1, blo1;
                LDSM4(bhe0, bho0, bhe1, bho1, sb + 2 * SM_BHI + bofs[p] + kbyte);
                LDSM4(ble0, blo0, ble1, blo1, sb + 2 * SM_BLO + bofs[p] + kbyte);
                mma16816(acc[2 * p],     ah0, ah1, ah2, ah3, bhe0, bhe1);
                mma16816(acc[2 * p],     ah0, ah1, ah2, ah3, ble0, ble1);
                mma16816(acc[2 * p],     al0, al1, al2, al3, bhe0, bhe1);
                mma16816(acc[2 * p + 1], ah0, ah1, ah2, ah3, bho0, bho1);
                mma16816(acc[2 * p + 1], ah0, ah1, ah2, ah3, blo0, blo1);
                mma16816(acc[2 * p + 1], al0, al1, al2, al3, bho0, bho1);
            }
        }
    }

    // ---- epilogue: emit fp16 h1
    int r0 = mBase + wid * 16 + g;
#pragma unroll
    for (int nt = 0; nt < 8; nt++) {
        int col = nt * 8 + t * 2;
        if (r0 < n)
            *(__half2*)&g_h1h[(size_t)r0 * HH + col] =
                __floats2half2_rn(acc[nt][0], acc[nt][1]);
        if (r0 + 8 < n)
            *(__half2*)&g_h1h[(size_t)(r0 + 8) * HH + col] =
                __floats2half2_rn(acc[nt][2], acc[nt][3]);
    }
}

// ---------------- layer-1 aggregate + bias + ReLU + @W2 ---------------------
// warp per dst; lane owns half2 slot 'lane'. Edge indices + weights staged
// lane-parallel in DOUBLE-BUFFERED smem: next block prefetched while current
// block's row gathers are in flight.
__global__ __launch_bounds__(256) void k_agg1(const float* __restrict__ b1,
                                              const float* __restrict__ W2,
                                              int n) {
    __shared__ float b1s[HH];
    __shared__ float w2t[CC * HH];
    __shared__ int   sc[8][2][32];
    __shared__ float swt[8][2][32];

    int tid = threadIdx.x;
    if (tid < HH) b1s[tid] = b1[tid];
    for (int i = tid; i < CC * HH; i += 256) {
        int c = i >> 6, k = i & 63;
        w2t[i] = W2[k * CC + c];
    }
    __syncthreads();

    int warp = tid >> 5, lane = tid & 31;
    int d = blockIdx.x * 8 + warp;
    if (d >= n) return;

    float dd = g_dinv[d];
    const __half2* h2 = (const __half2*)g_h1h;

    float2 self = __half22float2(__ldg(&h2[(size_t)d * 32 + lane]));
    float2 acc;                            // = sum dinv[s]*h[s] + dd*h[d]
    acc.x = self.x * dd;
    acc.y = self.y * dd;

    int e0 = g_rowptr[d];
    int e1 = g_rowptr[d + 1];
    int base = e0;
    int cnt = min(32, e1 - base);
    int buf = 0;
    if (cnt > 0 && lane < cnt) {
        int s = __ldg(&g_col[base + lane]);
        sc[warp][0][lane]  = s;
        swt[warp][0][lane] = __ldg(&g_dinv[s]);
    }
    __syncwarp();

    while (cnt > 0) {
        // prefetch next block into other buffer (overlaps current compute)
        int nbase = base + 32;
        int ncnt  = min(32, e1 - nbase);
        if (ncnt > 0 && lane < ncnt) {
            int s = __ldg(&g_col[nbase + lane]);
            sc[warp][buf ^ 1][lane]  = s;
            swt[warp][buf ^ 1][lane] = __ldg(&g_dinv[s]);
        }

        const int*   scb = sc[warp][buf];
        const float* swb = swt[warp][buf];
        int j = 0;
        for (; j + 4 <= cnt; j += 4) {
            int s0 = scb[j],     s1 = scb[j + 1];
            int s2 = scb[j + 2], s3 = scb[j + 3];
            float w0 = swb[j],     w1 = swb[j + 1];
            float w2 = swb[j + 2], w3 = swb[j + 3];
            float2 v0 = __half22float2(__ldg(&h2[(size_t)s0 * 32 + lane]));
            float2 v1 = __half22float2(__ldg(&h2[(size_t)s1 * 32 + lane]));
            float2 v2 = __half22float2(__ldg(&h2[(size_t)s2 * 32 + lane]));
            float2 v3 = __half22float2(__ldg(&h2[(size_t)s3 * 32 + lane]));
            acc.x += w0 * v0.x + w1 * v1.x + w2 * v2.x + w3 * v3.x;
            acc.y += w0 * v0.y + w1 * v1.y + w2 * v2.y + w3 * v3.y;
        }
        for (; j < cnt; j++) {
            int s = scb[j];
            float w = swb[j];
            float2 v = __half22float2(__ldg(&h2[(size_t)s * 32 + lane]));
            acc.x += w * v.x;
            acc.y += w * v.y;
        }
        __syncwarp();
        base = nbase;
        cnt  = ncnt;
        buf ^= 1;
    }

    float hx = fmaxf(dd * acc.x + b1s[2 * lane], 0.f);
    float hy = fmaxf(dd * acc.y + b1s[2 * lane + 1], 0.f);

    float pw[8];
#pragma unroll
    for (int c = 0; c < 8; c++) {
        float2 q = *(float2*)&w2t[c * HH + 2 * lane];
        pw[c] = hx * q.x + hy * q.y;
    }
#pragma unroll
    for (int c = 0; c < 8; c++) {
        pw[c] += __shfl_down_sync(0xffffffffu, pw[c], 16);
        pw[c] += __shfl_down_sync(0xffffffffu, pw[c], 8);
        pw[c] += __shfl_down_sync(0xffffffffu, pw[c], 4);
        pw[c] += __shfl_down_sync(0xffffffffu, pw[c], 2);
        pw[c] += __shfl_down_sync(0xffffffffu, pw[c], 1);
    }
    if (lane == 0) {
        // store t2' = dinv[d] * (relu(h) @ W2)  (pre-scaled for layer 2)
        *(float4*)&g_t2[(size_t)d * CC] =
            make_float4(dd * pw[0], dd * pw[1], dd * pw[2], dd * pw[3]);
        *(float4*)&g_t2[(size_t)d * CC + 4] =
            make_float4(dd * pw[4], dd * pw[5], dd * pw[6], dd * pw[7]);
    }
}

// ---------------- layer-2 aggregate + b2 -> out ------------------------------
// out[d] = dd * (sum_edges t2'[s] + t2'[d]) + b2 ; cols staged lane-parallel
// lane = j*8 + c; lane-j walks slots {j, j+4, j+8, ...} (stride 4, exhaustive)
__global__ __launch_bounds__(256) void k_agg2(const float* __restrict__ b2,
                                              float* __restrict__ out, int n) {
    __shared__ int sc[8][32];

    int tid  = threadIdx.x;
    int warp = tid >> 5, lane = tid & 31;
    int d = blockIdx.x * 8 + warp;
    if (d >= n) return;
    int j = lane >> 3, c = lane & 7;

    float dd  = g_dinv[d];
    int e0 = g_rowptr[d];
    int e1 = g_rowptr[d + 1];
    float acc = 0.f;
    for (int base = e0; base < e1; base += 32) {
        int cnt = min(32, e1 - base);
        if (lane < cnt) sc[warp][lane] = __ldg(&g_col[base + lane]);
        __syncwarp();
        int q = j;
        for (; q + 8 <= cnt; q += 8) {
            int s0 = sc[warp][q];
            int s1 = sc[warp][q + 4];
            float u0 = __ldg(&g_t2[(size_t)s0 * CC + c]);
            float u1 = __ldg(&g_t2[(size_t)s1 * CC + c]);
            acc += u0 + u1;
        }
        for (; q < cnt; q += 4)                 // exhaustive stride-4 tail
            acc += __ldg(&g_t2[(size_t)sc[warp][q] * CC + c]);
        __syncwarp();
    }
    acc += __shfl_down_sync(0xffffffffu, acc, 16);
    acc += __shfl_down_sync(0xffffffffu, acc, 8);
    if (j == 0) {
        float r = dd * (acc + g_t2[(size_t)d * CC + c]) + b2[c];
        out[(size_t)d * CC + c] = r;
    }
}

// ---------------- launch ------------------------------------------------------
extern "C" void kernel_launch(void* const* d_in, const int* in_sizes, int n_in,
                              void* d_out, int out_size) {
    const float* x  = (const float*)d_in[0];
    const int*   ei = (const int*)d_in[1];
    const float* W1 = (const float*)d_in[2];
    const float* b1 = (const float*)d_in[3];
    const float* W2 = (const float*)d_in[4];
    const float* b2 = (const float*)d_in[5];

    int n = in_sizes[0] / FIN;   // 100000
    int e = in_sizes[1] / 2;     // 3200000
    const int* src = ei;
    const int* dst = ei + e;

    int nb = (n + 255) / 256;

    cudaFuncSetAttribute(k_gemm1_mma, cudaFuncAttributeMaxDynamicSharedMemorySize,
                         SMEM_GEMM);

    void* degAddr = nullptr;
    cudaGetSymbolAddress(&degAddr, g_deg);

    if (g_s2) {
        // fork: GEMM path on g_s2, CSR path on main stream
        cudaEventRecord(g_evA, 0);
        cudaStreamWaitEvent(g_s2, g_evA, 0);
        k_prep_w1<<<(HH * FIN + 255) / 256, 256, 0, g_s2>>>(W1);
        k_gemm1_mma<<<(n + 127) / 128, 256, SMEM_GEMM, g_s2>>>(x, n);
        cudaEventRecord(g_evB, g_s2);

        cudaMemsetAsync(degAddr, 0, (size_t)n * sizeof(int), 0);
        k_hist<<<(e + 255) / 256, 256>>>(dst, e);
        k_bsum<<<nb, 256>>>(n);
        k_scan_bsum<<<1, 512>>>(nb);
        k_scan_final<<<nb, 256>>>(n, e);
        k_scatter<<<(e + 255) / 256, 256>>>(src, dst, e);

        cudaStreamWaitEvent(0, g_evB, 0);   // join
    } else {
        cudaMemsetAsync(degAddr, 0, (size_t)n * sizeof(int), 0);
        k_hist<<<(e + 255) / 256, 256>>>(dst, e);
        k_bsum<<<nb, 256>>>(n);
        k_scan_bsum<<<1, 512>>>(nb);
        k_scan_final<<<nb, 256>>>(n, e);
        k_scatter<<<(e + 255) / 256, 256>>>(src, dst, e);
        k_prep_w1<<<(HH * FIN + 255) / 256, 256>>>(W1);
        k_gemm1_mma<<<(n + 127) / 128, 256, SMEM_GEMM>>>(x, n);
    }

    k_agg1<<<(n + 7) / 8, 256>>>(b1, W2, n);
    k_agg2<<<(n + 7) / 8, 256>>>(b2, (float*)d_out, n);
}